// round 15
// baseline (speedup 1.0000x reference)
#include <cuda_runtime.h>
#include <cuda_fp16.h>
#include <math.h>
#include <stdint.h>

#define B_SZ 8192
#define D_SZ 256
#define TILE 128
#define NSTRIPES (B_SZ / TILE)                     // 64
#define NJOBS (NSTRIPES * (NSTRIPES + 1) / 2)      // 2080
#define GRID 152
#define NTHR 512
// sqrt(1/T * log2(e)) folded into fp16 embeddings -> epilogue is raw ex2
#define SCALE_H 4.5398159865f

#define S_STRIDE 264                               // 256 + 8 halves pad (ldmatrix conflict-free)
#define SLOT_HALVES (TILE * S_STRIDE)              // 33792
#define SLOT_BYTES (SLOT_HALVES * 2)               // 67584
#define IDS_BYTE_OFF (3 * SLOT_BYTES)              // 202752
#define SMEM_TOTAL (3 * SLOT_BYTES + 3 * TILE * 4) // 204288

static __device__ __half g_h[B_SZ * D_SZ];         // normalized*SCALE_H fp16 embeddings (4 MB)
static __device__ float g_rowAll[B_SZ];
static __device__ float g_rowPos[B_SZ];
static __device__ int g_done;                      // CTAs finished with job loop

// ---------- PTX helpers (baseline compute_103 features only) ----------
__device__ __forceinline__ uint32_t smem_u32(const void* p) {
    uint32_t a;
    asm("{ .reg .u64 t; cvta.to.shared.u64 t, %1; cvt.u32.u64 %0, t; }" : "=r"(a) : "l"(p));
    return a;
}
#define CP_ASYNC16(dst, src) \
    asm volatile("cp.async.cg.shared.global [%0], [%1], 16;" :: "r"(dst), "l"(src))
#define CP_COMMIT() asm volatile("cp.async.commit_group;" ::: "memory")
#define CP_WAIT0()  asm volatile("cp.async.wait_group 0;" ::: "memory")

#define LDSM_X4(r0, r1, r2, r3, a) \
    asm volatile("ldmatrix.sync.aligned.m8n8.x4.shared.b16 {%0,%1,%2,%3}, [%4];" \
                 : "=r"(r0), "=r"(r1), "=r"(r2), "=r"(r3) : "r"(a))

__device__ __forceinline__ void mma16(float* c, const uint32_t* a, const uint32_t* b) {
    asm volatile(
        "mma.sync.aligned.m16n8k16.row.col.f32.f16.f16.f32 "
        "{%0,%1,%2,%3}, {%4,%5,%6,%7}, {%8,%9}, {%0,%1,%2,%3};"
        : "+f"(c[0]), "+f"(c[1]), "+f"(c[2]), "+f"(c[3])
        : "r"(a[0]), "r"(a[1]), "r"(a[2]), "r"(a[3]), "r"(b[0]), "r"(b[1]));
}
__device__ __forceinline__ float ex2f(float x) {
    float r;
    asm("ex2.approx.f32 %0, %1;" : "=f"(r) : "f"(x));
    return r;
}
// packed fp16 ex2 (one MUFU op for two values)
__device__ __forceinline__ uint32_t hex2(uint32_t x) {
    uint32_t r;
    asm("ex2.approx.f16x2 %0, %1;" : "=r"(r) : "r"(x));
    return r;
}
__device__ __forceinline__ uint32_t h2u(__half2 h) { return *reinterpret_cast<uint32_t*>(&h); }
__device__ __forceinline__ __half2 u2h(uint32_t u) { return *reinterpret_cast<__half2*>(&u); }

// async-copy one 128x256 fp16 stripe + its 128 ids into a smem slot (512 threads)
__device__ __forceinline__ void load_stripe(uint32_t slot_base, uint32_t ids_base,
                                            int stripe, const int* ids, int tid) {
    const __half* src = g_h + (size_t)stripe * TILE * D_SZ;
#pragma unroll
    for (int p = 0; p < 8; p++) {
        int idx = tid + p * NTHR;
        int row = idx >> 5, ch = idx & 31;          // 32 x 16B chunks per row
        CP_ASYNC16(slot_base + (uint32_t)(row * S_STRIDE + ch * 8) * 2,
                   src + (size_t)row * D_SZ + ch * 8);
    }
    if (tid < 32)
        CP_ASYNC16(ids_base + tid * 16, ids + stripe * TILE + tid * 4);
}

// ---------- kernels ----------
// fp32 L2-normalize, 2 rows per warp (doubled MLP); fold in SCALE_H; zero accumulators
__global__ __launch_bounds__(256) void normalize_kernel(const float* __restrict__ emb) {
    int row0 = (blockIdx.x * 8 + (threadIdx.x >> 5)) * 2;
    int lane = threadIdx.x & 31;
    const float4* s0 = reinterpret_cast<const float4*>(emb) + (size_t)row0 * (D_SZ / 4);
    const float4* s1 = s0 + (D_SZ / 4);
    float4 a0 = s0[lane * 2], a1 = s0[lane * 2 + 1];
    float4 b0 = s1[lane * 2], b1 = s1[lane * 2 + 1];
    float sa = a0.x*a0.x + a0.y*a0.y + a0.z*a0.z + a0.w*a0.w
             + a1.x*a1.x + a1.y*a1.y + a1.z*a1.z + a1.w*a1.w;
    float sb = b0.x*b0.x + b0.y*b0.y + b0.z*b0.z + b0.w*b0.w
             + b1.x*b1.x + b1.y*b1.y + b1.z*b1.z + b1.w*b1.w;
#pragma unroll
    for (int o = 16; o > 0; o >>= 1) {
        sa += __shfl_xor_sync(0xffffffffu, sa, o);
        sb += __shfl_xor_sync(0xffffffffu, sb, o);
    }
    float ca = SCALE_H / fmaxf(sqrtf(sa), 1e-12f);
    float cb = SCALE_H / fmaxf(sqrtf(sb), 1e-12f);
    __half2 ha[4], hb[4];
    ha[0] = __floats2half2_rn(a0.x * ca, a0.y * ca);
    ha[1] = __floats2half2_rn(a0.z * ca, a0.w * ca);
    ha[2] = __floats2half2_rn(a1.x * ca, a1.y * ca);
    ha[3] = __floats2half2_rn(a1.z * ca, a1.w * ca);
    hb[0] = __floats2half2_rn(b0.x * cb, b0.y * cb);
    hb[1] = __floats2half2_rn(b0.z * cb, b0.w * cb);
    hb[2] = __floats2half2_rn(b1.x * cb, b1.y * cb);
    hb[3] = __floats2half2_rn(b1.z * cb, b1.w * cb);
    *reinterpret_cast<uint4*>(g_h + (size_t)row0 * D_SZ + lane * 8) =
        *reinterpret_cast<uint4*>(ha);
    *reinterpret_cast<uint4*>(g_h + (size_t)(row0 + 1) * D_SZ + lane * 8) =
        *reinterpret_cast<uint4*>(hb);
    if (lane == 0) {
        g_rowAll[row0] = 0.0f; g_rowPos[row0] = 0.0f;
        g_rowAll[row0 + 1] = 0.0f; g_rowPos[row0 + 1] = 0.0f;
    }
}

__global__ __launch_bounds__(NTHR, 1) void loss_kernel(const int* __restrict__ ids,
                                                       float* __restrict__ out) {
    extern __shared__ __half smh[];
    const uint32_t sb = smem_u32(smh);
    const uint32_t ids_sb = sb + IDS_BYTE_OFF;
    int* ids_s = reinterpret_cast<int*>(reinterpret_cast<char*>(smh) + IDS_BYTE_OFF);

    const int tid = threadIdx.x;
    const int lane = tid & 31, wid = tid >> 5;
    const int gid = lane >> 2, tig = lane & 3;
    const int wm = wid & 3, wn = wid >> 2;           // 4 (M) x 4 (N) warps, tile 32x32

    // ldmatrix per-lane offsets (half units)
    const int a_rowoff = (((lane >> 3) & 1) << 3) + (lane & 7);
    const int a_koff   = (lane >> 4) << 3;
    const uint32_t a_lane = (uint32_t)((wm * 32 + a_rowoff) * S_STRIDE + a_koff) * 2;
    const int b_noff = ((lane >> 4) << 3) + (lane & 7);
    const int b_koff = ((lane >> 3) & 1) << 3;
    const uint32_t b_lane = (uint32_t)((wn * 32 + b_noff) * S_STRIDE + b_koff) * 2;

    const int qs = (int)(((long long)blockIdx.x * NJOBS) / GRID);
    const int qe = (int)(((long long)(blockIdx.x + 1) * NJOBS) / GRID);

    int slot_stripe[3] = {-1, -1, -1};

    // resolve first job's (i, j) once; thereafter tracked incrementally
    int i = 0, j;
    {
        int base = 0;
        while (base + (NSTRIPES - i) <= qs) { base += NSTRIPES - i; i++; }
        j = i + (qs - base);
    }

    load_stripe(sb, ids_sb, i, ids, tid);
    slot_stripe[0] = i;
    if (j != i) {
        load_stripe(sb + SLOT_BYTES, ids_sb + TILE * 4, j, ids, tid);
        slot_stripe[1] = j;
    }
    CP_COMMIT();
    CP_WAIT0();
    __syncthreads();

    // cross-job fp32 row accumulators for the current stripe i (flushed on i change)
    float rAf[4] = {0.f, 0.f, 0.f, 0.f}, rPf[4] = {0.f, 0.f, 0.f, 0.f};

#pragma unroll 1
    for (int q = qs; q < qe; q++) {
        int slotA = 0, slotB = 0;
#pragma unroll
        for (int k = 0; k < 3; k++) {
            if (slot_stripe[k] == i) slotA = k;
            if (slot_stripe[k] == j) slotB = k;
        }

        // next job indices (incremental) + prefetch its single new stripe
        int ni = i, nj = j + 1;
        if (nj >= NSTRIPES) { ni = i + 1; nj = ni; }
        if (q + 1 < qe) {
            int ns = (ni != i && ni != j) ? ni : ((nj != i && nj != j) ? nj : -1);
            if (ns >= 0) {
                bool have = (slot_stripe[0] == ns) | (slot_stripe[1] == ns) | (slot_stripe[2] == ns);
                if (!have) {
                    int fs = 0;
#pragma unroll
                    for (int k = 2; k >= 0; k--)
                        if (k != slotA && k != slotB) fs = k;
                    load_stripe(sb + (uint32_t)fs * SLOT_BYTES, ids_sb + (uint32_t)fs * TILE * 4,
                                ns, ids, tid);
                    slot_stripe[fs] = ns;
                }
            }
            CP_COMMIT();
        }

        // ---- MMA: 128x128x256, warp tile 32x32 (2 mf x 4 nf fragments) ----
        const uint32_t a_base = sb + (uint32_t)slotA * SLOT_BYTES + a_lane;
        const uint32_t b_base = sb + (uint32_t)slotB * SLOT_BYTES + b_lane;
        float acc[2][4][4];
#pragma unroll
        for (int mf = 0; mf < 2; mf++)
#pragma unroll
            for (int nf = 0; nf < 4; nf++)
#pragma unroll
                for (int c = 0; c < 4; c++) acc[mf][nf][c] = 0.0f;

#pragma unroll
        for (int ks = 0; ks < 16; ks++) {
            uint32_t a[2][4], b[4][2];
#pragma unroll
            for (int mf = 0; mf < 2; mf++) {
                uint32_t addr = a_base + (uint32_t)(mf * 16 * S_STRIDE + ks * 16) * 2;
                LDSM_X4(a[mf][0], a[mf][1], a[mf][2], a[mf][3], addr);
            }
#pragma unroll
            for (int np = 0; np < 2; np++) {
                uint32_t addr = b_base + (uint32_t)(np * 16 * S_STRIDE + ks * 16) * 2;
                LDSM_X4(b[2*np][0], b[2*np][1], b[2*np+1][0], b[2*np+1][1], addr);
            }
#pragma unroll
            for (int mf = 0; mf < 2; mf++)
#pragma unroll
                for (int nf = 0; nf < 4; nf++)
                    mma16(acc[mf][nf], a[mf], b[nf]);
        }

        // ---- epilogue (packed fp16 math; diag job keeps fp32 pre-mask) ----
        const int* idA = ids_s + slotA * TILE;
        const int* idB = ids_s + slotB * TILE;

        __half2 rA2[4], rP2[4];
        const __half2 zero2 = __floats2half2_rn(0.0f, 0.0f);
#pragma unroll
        for (int r = 0; r < 4; r++) { rA2[r] = zero2; rP2[r] = zero2; }

        if (i != j) {
            __half2 myIdh2[4], idb2[4];
#pragma unroll
            for (int mf = 0; mf < 2; mf++)
#pragma unroll
                for (int h = 0; h < 2; h++) {
                    __half hv = __int2half_rn(idA[wm * 32 + mf * 16 + h * 8 + gid]);
                    myIdh2[mf * 2 + h] = __half2half2(hv);
                }
#pragma unroll
            for (int nf = 0; nf < 4; nf++) {
                const int colb = wn * 32 + nf * 8 + 2 * tig;
                idb2[nf] = __halves2half2(__int2half_rn(idB[colb]),
                                          __int2half_rn(idB[colb + 1]));
            }
            __half2 cA2[4], cP2[4];
#pragma unroll
            for (int nf = 0; nf < 4; nf++) { cA2[nf] = zero2; cP2[nf] = zero2; }

#pragma unroll
            for (int mf = 0; mf < 2; mf++) {
#pragma unroll
                for (int nf = 0; nf < 4; nf++) {
#pragma unroll
                    for (int h = 0; h < 2; h++) {
                        const int r = mf * 2 + h;
                        __half2 z = __floats2half2_rn(acc[mf][nf][2*h + 0],
                                                      acc[mf][nf][2*h + 1]);
                        __half2 e2 = u2h(hex2(h2u(z)));
                        rA2[r] = __hadd2(rA2[r], e2);
                        cA2[nf] = __hadd2(cA2[nf], e2);
                        __half2 m = __heq2(myIdh2[r], idb2[nf]);   // 1.0 / 0.0 per half
                        rP2[r] = __hfma2(e2, m, rP2[r]);
                        cP2[nf] = __hfma2(e2, m, cP2[nf]);
                    }
                }
            }
            // col side: fire-and-forget per-lane reductions (no shfl folds)
#pragma unroll
            for (int nf = 0; nf < 4; nf++) {
                const int colb = j * TILE + wn * 32 + nf * 8 + 2 * tig;
                float2 a2 = __half22float2(cA2[nf]);
                float2 p2 = __half22float2(cP2[nf]);
                atomicAdd(&g_rowAll[colb],     a2.x);
                atomicAdd(&g_rowAll[colb + 1], a2.y);
                atomicAdd(&g_rowPos[colb],     p2.x);
                atomicAdd(&g_rowPos[colb + 1], p2.y);
            }
        } else {
            // diag job: fp32 ex2 (diag value 2^20.6 would overflow fp16), mask, then pack
#pragma unroll
            for (int mf = 0; mf < 2; mf++) {
#pragma unroll
                for (int nf = 0; nf < 4; nf++) {
                    const int colb = wn * 32 + nf * 8 + 2 * tig;
                    const int idb0 = idB[colb], idb1 = idB[colb + 1];
#pragma unroll
                    for (int h = 0; h < 2; h++) {
                        const int r = mf * 2 + h;
                        const int rowl = wm * 32 + mf * 16 + h * 8 + gid;
                        const int myIdr = idA[rowl];
                        float e0 = ex2f(acc[mf][nf][2*h + 0]);
                        float e1 = ex2f(acc[mf][nf][2*h + 1]);
                        if (rowl == colb)     e0 = 0.0f;
                        if (rowl == colb + 1) e1 = 0.0f;
                        rA2[r] = __hadd2(rA2[r], __floats2half2_rn(e0, e1));
                        float p0 = (myIdr == idb0) ? e0 : 0.0f;
                        float p1 = (myIdr == idb1) ? e1 : 0.0f;
                        rP2[r] = __hadd2(rP2[r], __floats2half2_rn(p0, p1));
                    }
                }
            }
        }

        // row side: fold this job's half2 sums into the fp32 cross-job carriers
#pragma unroll
        for (int r = 0; r < 4; r++) {
            float2 a2 = __half22float2(rA2[r]);
            float2 p2 = __half22float2(rP2[r]);
            rAf[r] += a2.x + a2.y;
            rPf[r] += p2.x + p2.y;
        }
        // flush when stripe i retires (or at the very last job)
        if (ni != i || q + 1 == qe) {
#pragma unroll
            for (int r = 0; r < 4; r++) {
                int grow = i * TILE + wm * 32 + (r >> 1) * 16 + (r & 1) * 8 + gid;
                atomicAdd(&g_rowAll[grow], rAf[r]);
                atomicAdd(&g_rowPos[grow], rPf[r]);
                rAf[r] = 0.0f;
                rPf[r] = 0.0f;
            }
        }

        i = ni; j = nj;
        CP_WAIT0();
        __syncthreads();
    }

    // ---- tail: last CTA to finish reduces the 8192 rows and writes the loss ----
    __threadfence();
    __shared__ int s_rank;
    if (tid == 0) s_rank = atomicAdd(&g_done, 1);
    __syncthreads();
    if (s_rank == GRID - 1) {
        __threadfence();
        float* red = reinterpret_cast<float*>(smh);   // job loop done; reuse smem
        float pr = 0.0f, vd = 0.0f;
#pragma unroll
        for (int it = 0; it < B_SZ / NTHR; it++) {
            int r = tid + it * NTHR;
            float p = g_rowPos[r], a = g_rowAll[r];
            if (p > 0.0f) { pr += -logf(p / a); vd += 1.0f; }
        }
#pragma unroll
        for (int o = 16; o > 0; o >>= 1) {
            pr += __shfl_xor_sync(0xffffffffu, pr, o);
            vd += __shfl_xor_sync(0xffffffffu, vd, o);
        }
        if (lane == 0) { red[wid] = pr; red[32 + wid] = vd; }
        __syncthreads();
        if (tid < 16) {
            pr = red[tid]; vd = red[32 + tid];
#pragma unroll
            for (int o = 8; o > 0; o >>= 1) {
                pr += __shfl_xor_sync(0xffffu, pr, o);
                vd += __shfl_xor_sync(0xffffu, vd, o);
            }
            if (tid == 0) out[0] = pr / fmaxf(vd, 1.0f);
        }
        if (tid == 0) g_done = 0;   // reset for the next graph replay
    }
}

extern "C" void kernel_launch(void* const* d_in, const int* in_sizes, int n_in,
                              void* d_out, int out_size) {
    const float* emb = (const float*)d_in[0];
    const int*   ids = (const int*)d_in[1];
    float*       out = (float*)d_out;

    cudaFuncSetAttribute(loss_kernel, cudaFuncAttributeMaxDynamicSharedMemorySize, SMEM_TOTAL);

    normalize_kernel<<<B_SZ / 16, 256>>>(emb);
    loss_kernel<<<GRID, NTHR, SMEM_TOTAL>>>(ids, out);
}

// round 16
// speedup vs baseline: 1.8713x; 1.8713x over previous
#include <cuda_runtime.h>
#include <cuda_fp16.h>
#include <math.h>
#include <stdint.h>

#define B_SZ 8192
#define D_SZ 256
#define TILE 128
#define NSTRIPES (B_SZ / TILE)                     // 64
#define NJOBS (NSTRIPES * (NSTRIPES + 1) / 2)      // 2080
#define GRID 152
#define NTHR 512
// sqrt(1/T * log2(e)) folded into fp16 embeddings -> epilogue is raw ex2
#define SCALE_H 4.5398159865f

#define S_STRIDE 264                               // 256 + 8 halves pad (ldmatrix conflict-free)
#define SLOT_HALVES (TILE * S_STRIDE)              // 33792
#define SLOT_BYTES (SLOT_HALVES * 2)               // 67584
#define IDS_BYTE_OFF (3 * SLOT_BYTES)              // 202752
#define SMEM_TOTAL (3 * SLOT_BYTES + 3 * TILE * 4) // 204288

static __device__ __half g_h[B_SZ * D_SZ];         // normalized*SCALE_H fp16 embeddings (4 MB)
static __device__ float g_rowAll[B_SZ];
static __device__ float g_rowPos[B_SZ];
static __device__ int g_done;                      // CTAs finished with job loop

// ---------- PTX helpers (baseline compute_103 features only) ----------
__device__ __forceinline__ uint32_t smem_u32(const void* p) {
    uint32_t a;
    asm("{ .reg .u64 t; cvta.to.shared.u64 t, %1; cvt.u32.u64 %0, t; }" : "=r"(a) : "l"(p));
    return a;
}
#define CP_ASYNC16(dst, src) \
    asm volatile("cp.async.cg.shared.global [%0], [%1], 16;" :: "r"(dst), "l"(src))
#define CP_COMMIT() asm volatile("cp.async.commit_group;" ::: "memory")
#define CP_WAIT0()  asm volatile("cp.async.wait_group 0;" ::: "memory")

#define LDSM_X4(r0, r1, r2, r3, a) \
    asm volatile("ldmatrix.sync.aligned.m8n8.x4.shared.b16 {%0,%1,%2,%3}, [%4];" \
                 : "=r"(r0), "=r"(r1), "=r"(r2), "=r"(r3) : "r"(a))

__device__ __forceinline__ void mma16(float* c, const uint32_t* a, const uint32_t* b) {
    asm volatile(
        "mma.sync.aligned.m16n8k16.row.col.f32.f16.f16.f32 "
        "{%0,%1,%2,%3}, {%4,%5,%6,%7}, {%8,%9}, {%0,%1,%2,%3};"
        : "+f"(c[0]), "+f"(c[1]), "+f"(c[2]), "+f"(c[3])
        : "r"(a[0]), "r"(a[1]), "r"(a[2]), "r"(a[3]), "r"(b[0]), "r"(b[1]));
}
__device__ __forceinline__ float ex2f(float x) {
    float r;
    asm("ex2.approx.f32 %0, %1;" : "=f"(r) : "f"(x));
    return r;
}
// packed fp16 ex2 (one MUFU op for two values)
__device__ __forceinline__ uint32_t hex2(uint32_t x) {
    uint32_t r;
    asm("ex2.approx.f16x2 %0, %1;" : "=r"(r) : "r"(x));
    return r;
}
__device__ __forceinline__ uint32_t h2u(__half2 h) { return *reinterpret_cast<uint32_t*>(&h); }
__device__ __forceinline__ __half2 u2h(uint32_t u) { return *reinterpret_cast<__half2*>(&u); }

// async-copy one 128x256 fp16 stripe + its 128 ids into a smem slot (512 threads)
__device__ __forceinline__ void load_stripe(uint32_t slot_base, uint32_t ids_base,
                                            int stripe, const int* ids, int tid) {
    const __half* src = g_h + (size_t)stripe * TILE * D_SZ;
#pragma unroll
    for (int p = 0; p < 8; p++) {
        int idx = tid + p * NTHR;
        int row = idx >> 5, ch = idx & 31;          // 32 x 16B chunks per row
        CP_ASYNC16(slot_base + (uint32_t)(row * S_STRIDE + ch * 8) * 2,
                   src + (size_t)row * D_SZ + ch * 8);
    }
    if (tid < 32)
        CP_ASYNC16(ids_base + tid * 16, ids + stripe * TILE + tid * 4);
}

// ---------- kernels ----------
// fp32 L2-normalize, 2 rows per warp (doubled MLP); fold in SCALE_H; zero accumulators
__global__ __launch_bounds__(256) void normalize_kernel(const float* __restrict__ emb) {
    int row0 = (blockIdx.x * 8 + (threadIdx.x >> 5)) * 2;
    int lane = threadIdx.x & 31;
    const float4* s0 = reinterpret_cast<const float4*>(emb) + (size_t)row0 * (D_SZ / 4);
    const float4* s1 = s0 + (D_SZ / 4);
    float4 a0 = s0[lane * 2], a1 = s0[lane * 2 + 1];
    float4 b0 = s1[lane * 2], b1 = s1[lane * 2 + 1];
    float sa = a0.x*a0.x + a0.y*a0.y + a0.z*a0.z + a0.w*a0.w
             + a1.x*a1.x + a1.y*a1.y + a1.z*a1.z + a1.w*a1.w;
    float sb = b0.x*b0.x + b0.y*b0.y + b0.z*b0.z + b0.w*b0.w
             + b1.x*b1.x + b1.y*b1.y + b1.z*b1.z + b1.w*b1.w;
#pragma unroll
    for (int o = 16; o > 0; o >>= 1) {
        sa += __shfl_xor_sync(0xffffffffu, sa, o);
        sb += __shfl_xor_sync(0xffffffffu, sb, o);
    }
    float ca = SCALE_H / fmaxf(sqrtf(sa), 1e-12f);
    float cb = SCALE_H / fmaxf(sqrtf(sb), 1e-12f);
    __half2 ha[4], hb[4];
    ha[0] = __floats2half2_rn(a0.x * ca, a0.y * ca);
    ha[1] = __floats2half2_rn(a0.z * ca, a0.w * ca);
    ha[2] = __floats2half2_rn(a1.x * ca, a1.y * ca);
    ha[3] = __floats2half2_rn(a1.z * ca, a1.w * ca);
    hb[0] = __floats2half2_rn(b0.x * cb, b0.y * cb);
    hb[1] = __floats2half2_rn(b0.z * cb, b0.w * cb);
    hb[2] = __floats2half2_rn(b1.x * cb, b1.y * cb);
    hb[3] = __floats2half2_rn(b1.z * cb, b1.w * cb);
    *reinterpret_cast<uint4*>(g_h + (size_t)row0 * D_SZ + lane * 8) =
        *reinterpret_cast<uint4*>(ha);
    *reinterpret_cast<uint4*>(g_h + (size_t)(row0 + 1) * D_SZ + lane * 8) =
        *reinterpret_cast<uint4*>(hb);
    if (lane == 0) {
        g_rowAll[row0] = 0.0f; g_rowPos[row0] = 0.0f;
        g_rowAll[row0 + 1] = 0.0f; g_rowPos[row0 + 1] = 0.0f;
    }
}

__global__ __launch_bounds__(NTHR, 1) void loss_kernel(const int* __restrict__ ids,
                                                       float* __restrict__ out) {
    extern __shared__ __half smh[];
    const uint32_t sb = smem_u32(smh);
    const uint32_t ids_sb = sb + IDS_BYTE_OFF;
    int* ids_s = reinterpret_cast<int*>(reinterpret_cast<char*>(smh) + IDS_BYTE_OFF);

    const int tid = threadIdx.x;
    const int lane = tid & 31, wid = tid >> 5;
    const int gid = lane >> 2, tig = lane & 3;
    const int wm = wid & 3, wn = wid >> 2;           // 4 (M) x 4 (N) warps, tile 32x32

    // ldmatrix per-lane offsets (half units)
    const int a_rowoff = (((lane >> 3) & 1) << 3) + (lane & 7);
    const int a_koff   = (lane >> 4) << 3;
    const uint32_t a_lane = (uint32_t)((wm * 32 + a_rowoff) * S_STRIDE + a_koff) * 2;
    const int b_noff = ((lane >> 4) << 3) + (lane & 7);
    const int b_koff = ((lane >> 3) & 1) << 3;
    const uint32_t b_lane = (uint32_t)((wn * 32 + b_noff) * S_STRIDE + b_koff) * 2;

    const int qs = (int)(((long long)blockIdx.x * NJOBS) / GRID);
    const int qe = (int)(((long long)(blockIdx.x + 1) * NJOBS) / GRID);

    int slot_stripe[3] = {-1, -1, -1};

    // resolve first job's (i, j) once; thereafter tracked incrementally
    int i = 0, j;
    {
        int base = 0;
        while (base + (NSTRIPES - i) <= qs) { base += NSTRIPES - i; i++; }
        j = i + (qs - base);
    }

    load_stripe(sb, ids_sb, i, ids, tid);
    slot_stripe[0] = i;
    if (j != i) {
        load_stripe(sb + SLOT_BYTES, ids_sb + TILE * 4, j, ids, tid);
        slot_stripe[1] = j;
    }
    CP_COMMIT();
    CP_WAIT0();
    __syncthreads();

    // cross-job fp32 row accumulators for the current stripe i (flushed on i change)
    float rAf[4] = {0.f, 0.f, 0.f, 0.f}, rPf[4] = {0.f, 0.f, 0.f, 0.f};

#pragma unroll 1
    for (int q = qs; q < qe; q++) {
        int slotA = 0, slotB = 0;
#pragma unroll
        for (int k = 0; k < 3; k++) {
            if (slot_stripe[k] == i) slotA = k;
            if (slot_stripe[k] == j) slotB = k;
        }

        // next job indices (incremental) + prefetch its single new stripe
        int ni = i, nj = j + 1;
        if (nj >= NSTRIPES) { ni = i + 1; nj = ni; }
        if (q + 1 < qe) {
            int ns = (ni != i && ni != j) ? ni : ((nj != i && nj != j) ? nj : -1);
            if (ns >= 0) {
                bool have = (slot_stripe[0] == ns) | (slot_stripe[1] == ns) | (slot_stripe[2] == ns);
                if (!have) {
                    int fs = 0;
#pragma unroll
                    for (int k = 2; k >= 0; k--)
                        if (k != slotA && k != slotB) fs = k;
                    load_stripe(sb + (uint32_t)fs * SLOT_BYTES, ids_sb + (uint32_t)fs * TILE * 4,
                                ns, ids, tid);
                    slot_stripe[fs] = ns;
                }
            }
            CP_COMMIT();
        }

        // ---- MMA: 128x128x256, warp tile 32x32 (2 mf x 4 nf fragments) ----
        const uint32_t a_base = sb + (uint32_t)slotA * SLOT_BYTES + a_lane;
        const uint32_t b_base = sb + (uint32_t)slotB * SLOT_BYTES + b_lane;
        float acc[2][4][4];
#pragma unroll
        for (int mf = 0; mf < 2; mf++)
#pragma unroll
            for (int nf = 0; nf < 4; nf++)
#pragma unroll
                for (int c = 0; c < 4; c++) acc[mf][nf][c] = 0.0f;

#pragma unroll
        for (int ks = 0; ks < 16; ks++) {
            uint32_t a[2][4], b[4][2];
#pragma unroll
            for (int mf = 0; mf < 2; mf++) {
                uint32_t addr = a_base + (uint32_t)(mf * 16 * S_STRIDE + ks * 16) * 2;
                LDSM_X4(a[mf][0], a[mf][1], a[mf][2], a[mf][3], addr);
            }
#pragma unroll
            for (int np = 0; np < 2; np++) {
                uint32_t addr = b_base + (uint32_t)(np * 16 * S_STRIDE + ks * 16) * 2;
                LDSM_X4(b[2*np][0], b[2*np][1], b[2*np+1][0], b[2*np+1][1], addr);
            }
#pragma unroll
            for (int mf = 0; mf < 2; mf++)
#pragma unroll
                for (int nf = 0; nf < 4; nf++)
                    mma16(acc[mf][nf], a[mf], b[nf]);
        }

        // ---- epilogue (packed fp16 math; diag job keeps fp32 pre-mask) ----
        const int* idA = ids_s + slotA * TILE;
        const int* idB = ids_s + slotB * TILE;

        if (i != j) {
            __half2 rA2[4], rP2[4];
            const __half2 zero2 = __floats2half2_rn(0.0f, 0.0f);
#pragma unroll
            for (int r = 0; r < 4; r++) { rA2[r] = zero2; rP2[r] = zero2; }

            __half2 myIdh2[4], idb2[4];
#pragma unroll
            for (int mf = 0; mf < 2; mf++)
#pragma unroll
                for (int h = 0; h < 2; h++) {
                    __half hv = __int2half_rn(idA[wm * 32 + mf * 16 + h * 8 + gid]);
                    myIdh2[mf * 2 + h] = __half2half2(hv);
                }
#pragma unroll
            for (int nf = 0; nf < 4; nf++) {
                const int colb = wn * 32 + nf * 8 + 2 * tig;
                idb2[nf] = __halves2half2(__int2half_rn(idB[colb]),
                                          __int2half_rn(idB[colb + 1]));
            }
            __half2 cA2[4], cP2[4];
#pragma unroll
            for (int nf = 0; nf < 4; nf++) { cA2[nf] = zero2; cP2[nf] = zero2; }

#pragma unroll
            for (int mf = 0; mf < 2; mf++) {
#pragma unroll
                for (int nf = 0; nf < 4; nf++) {
#pragma unroll
                    for (int h = 0; h < 2; h++) {
                        const int r = mf * 2 + h;
                        __half2 z = __floats2half2_rn(acc[mf][nf][2*h + 0],
                                                      acc[mf][nf][2*h + 1]);
                        __half2 e2 = u2h(hex2(h2u(z)));
                        rA2[r] = __hadd2(rA2[r], e2);
                        cA2[nf] = __hadd2(cA2[nf], e2);
                        __half2 m = __heq2(myIdh2[r], idb2[nf]);   // 1.0 / 0.0 per half
                        rP2[r] = __hfma2(e2, m, rP2[r]);
                        cP2[nf] = __hfma2(e2, m, cP2[nf]);
                    }
                }
            }
            // col fold across gid (xor 4, 8) on packed half2; writers gid 0/4 (4 per addr)
#pragma unroll
            for (int nf = 0; nf < 4; nf++) {
                uint32_t va = h2u(cA2[nf]), vp = h2u(cP2[nf]);
                va = h2u(__hadd2(u2h(va), u2h(__shfl_xor_sync(0xffffffffu, va, 4))));
                va = h2u(__hadd2(u2h(va), u2h(__shfl_xor_sync(0xffffffffu, va, 8))));
                vp = h2u(__hadd2(u2h(vp), u2h(__shfl_xor_sync(0xffffffffu, vp, 4))));
                vp = h2u(__hadd2(u2h(vp), u2h(__shfl_xor_sync(0xffffffffu, vp, 8))));
                if ((gid & 3) == 0) {
                    const int colb = j * TILE + wn * 32 + nf * 8 + 2 * tig;
                    float2 a2 = __half22float2(u2h(va));
                    float2 p2 = __half22float2(u2h(vp));
                    atomicAdd(&g_rowAll[colb],     a2.x);
                    atomicAdd(&g_rowAll[colb + 1], a2.y);
                    atomicAdd(&g_rowPos[colb],     p2.x);
                    atomicAdd(&g_rowPos[colb + 1], p2.y);
                }
            }
            // row side: fold this job's half2 sums into the fp32 cross-job carriers
#pragma unroll
            for (int r = 0; r < 4; r++) {
                float2 a2 = __half22float2(rA2[r]);
                float2 p2 = __half22float2(rP2[r]);
                rAf[r] += a2.x + a2.y;
                rPf[r] += p2.x + p2.y;
            }
        } else {
            // diag job: fp32 ex2 (diag value 2^20.6 would overflow fp16), mask, accumulate fp32
#pragma unroll
            for (int mf = 0; mf < 2; mf++) {
#pragma unroll
                for (int nf = 0; nf < 4; nf++) {
                    const int colb = wn * 32 + nf * 8 + 2 * tig;
                    const int idb0 = idB[colb], idb1 = idB[colb + 1];
#pragma unroll
                    for (int h = 0; h < 2; h++) {
                        const int r = mf * 2 + h;
                        const int rowl = wm * 32 + mf * 16 + h * 8 + gid;
                        const int myIdr = idA[rowl];
                        float e0 = ex2f(acc[mf][nf][2*h + 0]);
                        float e1 = ex2f(acc[mf][nf][2*h + 1]);
                        if (rowl == colb)     e0 = 0.0f;
                        if (rowl == colb + 1) e1 = 0.0f;
                        rAf[r] += e0 + e1;
                        rPf[r] += ((myIdr == idb0) ? e0 : 0.0f)
                                + ((myIdr == idb1) ? e1 : 0.0f);
                    }
                }
            }
        }

        // flush row carriers when stripe i retires (or at the very last job)
        if (ni != i || q + 1 == qe) {
#pragma unroll
            for (int r = 0; r < 4; r++) {
                float va = rAf[r], vp = rPf[r];
                va += __shfl_xor_sync(0xffffffffu, va, 1);
                va += __shfl_xor_sync(0xffffffffu, va, 2);
                vp += __shfl_xor_sync(0xffffffffu, vp, 1);
                vp += __shfl_xor_sync(0xffffffffu, vp, 2);
                if (tig == 0) {
                    int grow = i * TILE + wm * 32 + (r >> 1) * 16 + (r & 1) * 8 + gid;
                    atomicAdd(&g_rowAll[grow], va);
                    atomicAdd(&g_rowPos[grow], vp);
                }
                rAf[r] = 0.0f;
                rPf[r] = 0.0f;
            }
        }

        i = ni; j = nj;
        CP_WAIT0();
        __syncthreads();
    }

    // ---- tail: last CTA to finish reduces the 8192 rows and writes the loss ----
    __threadfence();
    __shared__ int s_rank;
    if (tid == 0) s_rank = atomicAdd(&g_done, 1);
    __syncthreads();
    if (s_rank == GRID - 1) {
        __threadfence();
        float* red = reinterpret_cast<float*>(smh);   // job loop done; reuse smem
        float pr = 0.0f, vd = 0.0f;
#pragma unroll
        for (int it = 0; it < B_SZ / NTHR; it++) {
            int r = tid + it * NTHR;
            float p = g_rowPos[r], a = g_rowAll[r];
            if (p > 0.0f) { pr += -logf(p / a); vd += 1.0f; }
        }
#pragma unroll
        for (int o = 16; o > 0; o >>= 1) {
            pr += __shfl_xor_sync(0xffffffffu, pr, o);
            vd += __shfl_xor_sync(0xffffffffu, vd, o);
        }
        if (lane == 0) { red[wid] = pr; red[32 + wid] = vd; }
        __syncthreads();
        if (tid < 16) {
            pr = red[tid]; vd = red[32 + tid];
#pragma unroll
            for (int o = 8; o > 0; o >>= 1) {
                pr += __shfl_xor_sync(0xffffu, pr, o);
                vd += __shfl_xor_sync(0xffffu, vd, o);
            }
            if (tid == 0) out[0] = pr / fmaxf(vd, 1.0f);
        }
        if (tid == 0) g_done = 0;   // reset for the next graph replay
    }
}

extern "C" void kernel_launch(void* const* d_in, const int* in_sizes, int n_in,
                              void* d_out, int out_size) {
    const float* emb = (const float*)d_in[0];
    const int*   ids = (const int*)d_in[1];
    float*       out = (float*)d_out;

    cudaFuncSetAttribute(loss_kernel, cudaFuncAttributeMaxDynamicSharedMemorySize, SMEM_TOTAL);

    normalize_kernel<<<B_SZ / 16, 256>>>(emb);
    loss_kernel<<<GRID, NTHR, SMEM_TOTAL>>>(ids, out);
}

// round 17
// speedup vs baseline: 1.8805x; 1.0049x over previous
#include <cuda_runtime.h>
#include <cuda_fp16.h>
#include <math.h>
#include <stdint.h>

#define B_SZ 8192
#define D_SZ 256
#define TILE 128
#define NSTRIPES (B_SZ / TILE)                     // 64
#define NJOBS (NSTRIPES * (NSTRIPES + 1) / 2)      // 2080
#define GRID 152
#define NTHR 512
// sqrt(1/T * log2(e)) folded into fp16 embeddings -> epilogue is raw ex2
#define SCALE_H 4.5398159865f

#define S_STRIDE 264                               // 256 + 8 halves pad (ldmatrix conflict-free)
#define SLOT_HALVES (TILE * S_STRIDE)              // 33792
#define SLOT_BYTES (SLOT_HALVES * 2)               // 67584
#define IDS_BYTE_OFF (3 * SLOT_BYTES)              // 202752; per slot: 128 half ids (256B)
#define SMEM_TOTAL (3 * SLOT_BYTES + 3 * TILE * 2) // 203520

static __device__ __half g_h[B_SZ * D_SZ];         // normalized*SCALE_H fp16 embeddings (4 MB)
static __device__ __half g_idh[B_SZ];              // ids as fp16 (exact: ids < 1024)
static __device__ float g_rowAll[B_SZ];
static __device__ float g_rowPos[B_SZ];
static __device__ int g_done;                      // CTAs finished with job loop

// ---------- PTX helpers (baseline compute_103 features only) ----------
__device__ __forceinline__ uint32_t smem_u32(const void* p) {
    uint32_t a;
    asm("{ .reg .u64 t; cvta.to.shared.u64 t, %1; cvt.u32.u64 %0, t; }" : "=r"(a) : "l"(p));
    return a;
}
#define CP_ASYNC16(dst, src) \
    asm volatile("cp.async.cg.shared.global [%0], [%1], 16;" :: "r"(dst), "l"(src))
#define CP_COMMIT() asm volatile("cp.async.commit_group;" ::: "memory")
#define CP_WAIT0()  asm volatile("cp.async.wait_group 0;" ::: "memory")

#define LDSM_X4(r0, r1, r2, r3, a) \
    asm volatile("ldmatrix.sync.aligned.m8n8.x4.shared.b16 {%0,%1,%2,%3}, [%4];" \
                 : "=r"(r0), "=r"(r1), "=r"(r2), "=r"(r3) : "r"(a))

__device__ __forceinline__ void mma16(float* c, const uint32_t* a, const uint32_t* b) {
    asm volatile(
        "mma.sync.aligned.m16n8k16.row.col.f32.f16.f16.f32 "
        "{%0,%1,%2,%3}, {%4,%5,%6,%7}, {%8,%9}, {%0,%1,%2,%3};"
        : "+f"(c[0]), "+f"(c[1]), "+f"(c[2]), "+f"(c[3])
        : "r"(a[0]), "r"(a[1]), "r"(a[2]), "r"(a[3]), "r"(b[0]), "r"(b[1]));
}
__device__ __forceinline__ float ex2f(float x) {
    float r;
    asm("ex2.approx.f32 %0, %1;" : "=f"(r) : "f"(x));
    return r;
}
// packed fp16 ex2 (one MUFU op for two values)
__device__ __forceinline__ uint32_t hex2(uint32_t x) {
    uint32_t r;
    asm("ex2.approx.f16x2 %0, %1;" : "=r"(r) : "r"(x));
    return r;
}
__device__ __forceinline__ uint32_t h2u(__half2 h) { return *reinterpret_cast<uint32_t*>(&h); }
__device__ __forceinline__ __half2 u2h(uint32_t u) { return *reinterpret_cast<__half2*>(&u); }

// async-copy one 128x256 fp16 stripe + its 128 half-ids into a smem slot (512 threads)
__device__ __forceinline__ void load_stripe(uint32_t slot_base, uint32_t ids_base,
                                            int stripe, int tid) {
    const __half* src = g_h + (size_t)stripe * TILE * D_SZ;
#pragma unroll
    for (int p = 0; p < 8; p++) {
        int idx = tid + p * NTHR;
        int row = idx >> 5, ch = idx & 31;          // 32 x 16B chunks per row
        CP_ASYNC16(slot_base + (uint32_t)(row * S_STRIDE + ch * 8) * 2,
                   src + (size_t)row * D_SZ + ch * 8);
    }
    if (tid < 16)   // 128 halves = 256 B
        CP_ASYNC16(ids_base + tid * 16, g_idh + stripe * TILE + tid * 8);
}

// ---------- kernels ----------
// fp32 L2-normalize, 2 rows per warp; fold in SCALE_H; write half ids; zero accumulators
__global__ __launch_bounds__(256) void normalize_kernel(const float* __restrict__ emb,
                                                        const int* __restrict__ ids) {
    int row0 = (blockIdx.x * 8 + (threadIdx.x >> 5)) * 2;
    int lane = threadIdx.x & 31;
    const float4* s0 = reinterpret_cast<const float4*>(emb) + (size_t)row0 * (D_SZ / 4);
    const float4* s1 = s0 + (D_SZ / 4);
    float4 a0 = s0[lane * 2], a1 = s0[lane * 2 + 1];
    float4 b0 = s1[lane * 2], b1 = s1[lane * 2 + 1];
    float sa = a0.x*a0.x + a0.y*a0.y + a0.z*a0.z + a0.w*a0.w
             + a1.x*a1.x + a1.y*a1.y + a1.z*a1.z + a1.w*a1.w;
    float sb = b0.x*b0.x + b0.y*b0.y + b0.z*b0.z + b0.w*b0.w
             + b1.x*b1.x + b1.y*b1.y + b1.z*b1.z + b1.w*b1.w;
#pragma unroll
    for (int o = 16; o > 0; o >>= 1) {
        sa += __shfl_xor_sync(0xffffffffu, sa, o);
        sb += __shfl_xor_sync(0xffffffffu, sb, o);
    }
    float ca = SCALE_H / fmaxf(sqrtf(sa), 1e-12f);
    float cb = SCALE_H / fmaxf(sqrtf(sb), 1e-12f);
    __half2 ha[4], hb[4];
    ha[0] = __floats2half2_rn(a0.x * ca, a0.y * ca);
    ha[1] = __floats2half2_rn(a0.z * ca, a0.w * ca);
    ha[2] = __floats2half2_rn(a1.x * ca, a1.y * ca);
    ha[3] = __floats2half2_rn(a1.z * ca, a1.w * ca);
    hb[0] = __floats2half2_rn(b0.x * cb, b0.y * cb);
    hb[1] = __floats2half2_rn(b0.z * cb, b0.w * cb);
    hb[2] = __floats2half2_rn(b1.x * cb, b1.y * cb);
    hb[3] = __floats2half2_rn(b1.z * cb, b1.w * cb);
    *reinterpret_cast<uint4*>(g_h + (size_t)row0 * D_SZ + lane * 8) =
        *reinterpret_cast<uint4*>(ha);
    *reinterpret_cast<uint4*>(g_h + (size_t)(row0 + 1) * D_SZ + lane * 8) =
        *reinterpret_cast<uint4*>(hb);
    if (lane == 0) {
        g_idh[row0]     = __int2half_rn(ids[row0]);
        g_idh[row0 + 1] = __int2half_rn(ids[row0 + 1]);
        g_rowAll[row0] = 0.0f; g_rowPos[row0] = 0.0f;
        g_rowAll[row0 + 1] = 0.0f; g_rowPos[row0 + 1] = 0.0f;
    }
}

__global__ __launch_bounds__(NTHR, 1) void loss_kernel(float* __restrict__ out) {
    extern __shared__ __half smh[];
    const uint32_t sb = smem_u32(smh);
    const uint32_t ids_sb = sb + IDS_BYTE_OFF;
    const __half* ids_h = smh + IDS_BYTE_OFF / 2;

    const int tid = threadIdx.x;
    const int lane = tid & 31, wid = tid >> 5;
    const int gid = lane >> 2, tig = lane & 3;
    const int wm = wid & 3, wn = wid >> 2;           // 4 (M) x 4 (N) warps, tile 32x32

    // ldmatrix per-lane offsets (half units)
    const int a_rowoff = (((lane >> 3) & 1) << 3) + (lane & 7);
    const int a_koff   = (lane >> 4) << 3;
    const uint32_t a_lane = (uint32_t)((wm * 32 + a_rowoff) * S_STRIDE + a_koff) * 2;
    const int b_noff = ((lane >> 4) << 3) + (lane & 7);
    const int b_koff = ((lane >> 3) & 1) << 3;
    const uint32_t b_lane = (uint32_t)((wn * 32 + b_noff) * S_STRIDE + b_koff) * 2;

    const int qs = (int)(((long long)blockIdx.x * NJOBS) / GRID);
    const int qe = (int)(((long long)(blockIdx.x + 1) * NJOBS) / GRID);

    int slot_stripe[3] = {-1, -1, -1};

    // resolve first job's (i, j) once; thereafter tracked incrementally
    int i = 0, j;
    {
        int base = 0;
        while (base + (NSTRIPES - i) <= qs) { base += NSTRIPES - i; i++; }
        j = i + (qs - base);
    }

    load_stripe(sb, ids_sb, i, tid);
    slot_stripe[0] = i;
    if (j != i) {
        load_stripe(sb + SLOT_BYTES, ids_sb + TILE * 2, j, tid);
        slot_stripe[1] = j;
    }
    CP_COMMIT();
    CP_WAIT0();
    __syncthreads();

    // cross-job fp32 row accumulators for the current stripe i (flushed on i change)
    float rAf[4] = {0.f, 0.f, 0.f, 0.f}, rPf[4] = {0.f, 0.f, 0.f, 0.f};

#pragma unroll 1
    for (int q = qs; q < qe; q++) {
        int slotA = 0, slotB = 0;
#pragma unroll
        for (int k = 0; k < 3; k++) {
            if (slot_stripe[k] == i) slotA = k;
            if (slot_stripe[k] == j) slotB = k;
        }

        // next job indices (incremental) + prefetch its single new stripe
        int ni = i, nj = j + 1;
        if (nj >= NSTRIPES) { ni = i + 1; nj = ni; }
        if (q + 1 < qe) {
            int ns = (ni != i && ni != j) ? ni : ((nj != i && nj != j) ? nj : -1);
            if (ns >= 0) {
                bool have = (slot_stripe[0] == ns) | (slot_stripe[1] == ns) | (slot_stripe[2] == ns);
                if (!have) {
                    int fs = 0;
#pragma unroll
                    for (int k = 2; k >= 0; k--)
                        if (k != slotA && k != slotB) fs = k;
                    load_stripe(sb + (uint32_t)fs * SLOT_BYTES, ids_sb + (uint32_t)fs * TILE * 2,
                                ns, tid);
                    slot_stripe[fs] = ns;
                }
            }
            CP_COMMIT();
        }

        // ---- MMA: 128x128x256, warp tile 32x32 (2 mf x 4 nf fragments) ----
        const uint32_t a_base = sb + (uint32_t)slotA * SLOT_BYTES + a_lane;
        const uint32_t b_base = sb + (uint32_t)slotB * SLOT_BYTES + b_lane;
        float acc[2][4][4];
#pragma unroll
        for (int mf = 0; mf < 2; mf++)
#pragma unroll
            for (int nf = 0; nf < 4; nf++)
#pragma unroll
                for (int c = 0; c < 4; c++) acc[mf][nf][c] = 0.0f;

#pragma unroll
        for (int ks = 0; ks < 16; ks++) {
            uint32_t a[2][4], b[4][2];
#pragma unroll
            for (int mf = 0; mf < 2; mf++) {
                uint32_t addr = a_base + (uint32_t)(mf * 16 * S_STRIDE + ks * 16) * 2;
                LDSM_X4(a[mf][0], a[mf][1], a[mf][2], a[mf][3], addr);
            }
#pragma unroll
            for (int np = 0; np < 2; np++) {
                uint32_t addr = b_base + (uint32_t)(np * 16 * S_STRIDE + ks * 16) * 2;
                LDSM_X4(b[2*np][0], b[2*np][1], b[2*np+1][0], b[2*np+1][1], addr);
            }
#pragma unroll
            for (int mf = 0; mf < 2; mf++)
#pragma unroll
                for (int nf = 0; nf < 4; nf++)
                    mma16(acc[mf][nf], a[mf], b[nf]);
        }

        // ---- epilogue (packed fp16 math; half ids; diag job keeps fp32 pre-mask) ----
        const __half* idA = ids_h + slotA * TILE;
        const __half* idB = ids_h + slotB * TILE;

        if (i != j) {
            __half2 rA2[4], rP2[4];
            const __half2 zero2 = __floats2half2_rn(0.0f, 0.0f);
#pragma unroll
            for (int r = 0; r < 4; r++) { rA2[r] = zero2; rP2[r] = zero2; }

            __half2 myIdh2[4], idb2[4];
#pragma unroll
            for (int mf = 0; mf < 2; mf++)
#pragma unroll
                for (int h = 0; h < 2; h++)
                    myIdh2[mf * 2 + h] = __half2half2(idA[wm * 32 + mf * 16 + h * 8 + gid]);
#pragma unroll
            for (int nf = 0; nf < 4; nf++) {
                const int colb = wn * 32 + nf * 8 + 2 * tig;   // even -> aligned half2
                idb2[nf] = *reinterpret_cast<const __half2*>(idB + colb);
            }
            __half2 cA2[4], cP2[4];
#pragma unroll
            for (int nf = 0; nf < 4; nf++) { cA2[nf] = zero2; cP2[nf] = zero2; }

#pragma unroll
            for (int mf = 0; mf < 2; mf++) {
#pragma unroll
                for (int nf = 0; nf < 4; nf++) {
#pragma unroll
                    for (int h = 0; h < 2; h++) {
                        const int r = mf * 2 + h;
                        __half2 z = __floats2half2_rn(acc[mf][nf][2*h + 0],
                                                      acc[mf][nf][2*h + 1]);
                        __half2 e2 = u2h(hex2(h2u(z)));
                        rA2[r] = __hadd2(rA2[r], e2);
                        cA2[nf] = __hadd2(cA2[nf], e2);
                        __half2 m = __heq2(myIdh2[r], idb2[nf]);   // 1.0 / 0.0 per half
                        rP2[r] = __hfma2(e2, m, rP2[r]);
                        cP2[nf] = __hfma2(e2, m, cP2[nf]);
                    }
                }
            }
            // col fold across gid (xor 4, 8) on packed half2; writers gid 0/4 (4 per addr)
#pragma unroll
            for (int nf = 0; nf < 4; nf++) {
                uint32_t va = h2u(cA2[nf]), vp = h2u(cP2[nf]);
                va = h2u(__hadd2(u2h(va), u2h(__shfl_xor_sync(0xffffffffu, va, 4))));
                va = h2u(__hadd2(u2h(va), u2h(__shfl_xor_sync(0xffffffffu, va, 8))));
                vp = h2u(__hadd2(u2h(vp), u2h(__shfl_xor_sync(0xffffffffu, vp, 4))));
                vp = h2u(__hadd2(u2h(vp), u2h(__shfl_xor_sync(0xffffffffu, vp, 8))));
                if ((gid & 3) == 0) {
                    const int colb = j * TILE + wn * 32 + nf * 8 + 2 * tig;
                    float2 a2 = __half22float2(u2h(va));
                    float2 p2 = __half22float2(u2h(vp));
                    atomicAdd(&g_rowAll[colb],     a2.x);
                    atomicAdd(&g_rowAll[colb + 1], a2.y);
                    atomicAdd(&g_rowPos[colb],     p2.x);
                    atomicAdd(&g_rowPos[colb + 1], p2.y);
                }
            }
            // row side: fold this job's half2 sums into the fp32 cross-job carriers
#pragma unroll
            for (int r = 0; r < 4; r++) {
                float2 a2 = __half22float2(rA2[r]);
                float2 p2 = __half22float2(rP2[r]);
                rAf[r] += a2.x + a2.y;
                rPf[r] += p2.x + p2.y;
            }
        } else {
            // diag job: fp32 ex2 (diag value 2^20.6 would overflow fp16), mask, accumulate fp32
#pragma unroll
            for (int mf = 0; mf < 2; mf++) {
#pragma unroll
                for (int nf = 0; nf < 4; nf++) {
                    const int colb = wn * 32 + nf * 8 + 2 * tig;
                    const __half idb0 = idB[colb], idb1 = idB[colb + 1];
#pragma unroll
                    for (int h = 0; h < 2; h++) {
                        const int r = mf * 2 + h;
                        const int rowl = wm * 32 + mf * 16 + h * 8 + gid;
                        const __half myIdr = idA[rowl];
                        float e0 = ex2f(acc[mf][nf][2*h + 0]);
                        float e1 = ex2f(acc[mf][nf][2*h + 1]);
                        if (rowl == colb)     e0 = 0.0f;
                        if (rowl == colb + 1) e1 = 0.0f;
                        rAf[r] += e0 + e1;
                        rPf[r] += (__heq(myIdr, idb0) ? e0 : 0.0f)
                                + (__heq(myIdr, idb1) ? e1 : 0.0f);
                    }
                }
            }
        }

        // flush row carriers when stripe i retires (or at the very last job)
        if (ni != i || q + 1 == qe) {
#pragma unroll
            for (int r = 0; r < 4; r++) {
                float va = rAf[r], vp = rPf[r];
                va += __shfl_xor_sync(0xffffffffu, va, 1);
                va += __shfl_xor_sync(0xffffffffu, va, 2);
                vp += __shfl_xor_sync(0xffffffffu, vp, 1);
                vp += __shfl_xor_sync(0xffffffffu, vp, 2);
                if (tig == 0) {
                    int grow = i * TILE + wm * 32 + (r >> 1) * 16 + (r & 1) * 8 + gid;
                    atomicAdd(&g_rowAll[grow], va);
                    atomicAdd(&g_rowPos[grow], vp);
                }
                rAf[r] = 0.0f;
                rPf[r] = 0.0f;
            }
        }

        i = ni; j = nj;
        CP_WAIT0();
        __syncthreads();
    }

    // ---- tail: last CTA to finish reduces the 8192 rows and writes the loss ----
    __threadfence();
    __shared__ int s_rank;
    if (tid == 0) s_rank = atomicAdd(&g_done, 1);
    __syncthreads();
    if (s_rank == GRID - 1) {
        __threadfence();
        float* red = reinterpret_cast<float*>(smh);   // job loop done; reuse smem
        float pr = 0.0f, vd = 0.0f;
#pragma unroll
        for (int it = 0; it < B_SZ / NTHR; it++) {
            int r = tid + it * NTHR;
            float p = g_rowPos[r], a = g_rowAll[r];
            if (p > 0.0f) { pr += -logf(p / a); vd += 1.0f; }
        }
#pragma unroll
        for (int o = 16; o > 0; o >>= 1) {
            pr += __shfl_xor_sync(0xffffffffu, pr, o);
            vd += __shfl_xor_sync(0xffffffffu, vd, o);
        }
        if (lane == 0) { red[wid] = pr; red[32 + wid] = vd; }
        __syncthreads();
        if (tid < 16) {
            pr = red[tid]; vd = red[32 + tid];
#pragma unroll
            for (int o = 8; o > 0; o >>= 1) {
                pr += __shfl_xor_sync(0xffffu, pr, o);
                vd += __shfl_xor_sync(0xffffu, vd, o);
            }
            if (tid == 0) out[0] = pr / fmaxf(vd, 1.0f);
        }
        if (tid == 0) g_done = 0;   // reset for the next graph replay
    }
}

extern "C" void kernel_launch(void* const* d_in, const int* in_sizes, int n_in,
                              void* d_out, int out_size) {
    const float* emb = (const float*)d_in[0];
    const int*   ids = (const int*)d_in[1];
    float*       out = (float*)d_out;

    cudaFuncSetAttribute(loss_kernel, cudaFuncAttributeMaxDynamicSharedMemorySize, SMEM_TOTAL);

    normalize_kernel<<<B_SZ / 16, 256>>>(emb, ids);
    loss_kernel<<<GRID, NTHR, SMEM_TOTAL>>>(out);
}